// round 14
// baseline (speedup 1.0000x reference)
#include <cuda_runtime.h>
#include <math.h>

#define Nn   10000
#define Ee   320000
#define EA   (Ee + Nn)        // augmented edges (self loops appended at the end)
#define HIDC 256
#define INC  4

// ---------------- scratch (device globals; no allocation allowed) ----------
__device__ float d_la[Nn];                 // sum of incoming edge attr
__device__ float d_deg[Nn];                // incoming real-edge count
__device__ int   d_off[Nn];                // CSR offsets (exclusive)
__device__ int   d_cur[Nn];                // fill cursors
__device__ int   d_btot[64];
__device__ int   d_csrc[EA];               // CSR: src node per slot
__device__ float d_cea[EA];                // CSR: edge attr per slot (self-loop = mean)
__device__ float d_xl1[Nn * HIDC];
__device__ float d_xr1[Nn * HIDC];
__device__ float d_h1ln[Nn * HIDC];
__device__ float d_xl2[Nn * HIDC];
__device__ float d_xr2[Nn * HIDC];
__device__ float d_h2ln[Nn * HIDC];
__device__ float d_pol[Nn * INC];

__device__ __forceinline__ float lrelu(float v) { return v > 0.f ? v : 0.2f * v; }

// packed fp32x2 helpers (Blackwell f32x2 PTX family)
__device__ __forceinline__ unsigned long long pack_f32x2(float lo, float hi) {
    unsigned long long r;
    asm("mov.b64 %0, {%1, %2};" : "=l"(r) : "f"(lo), "f"(hi));
    return r;
}
__device__ __forceinline__ void fma_f32x2(unsigned long long& acc,
                                          unsigned long long a, unsigned long long b) {
    asm("fma.rn.f32x2 %0, %1, %2, %0;" : "+l"(acc) : "l"(a), "l"(b));
}
__device__ __forceinline__ float hsum_f32x2(unsigned long long p) {
    float lo, hi;
    asm("mov.b64 {%0, %1}, %2;" : "=f"(lo), "=f"(hi) : "l"(p));
    return lo + hi;
}

// ---------------- init ------------------------------------------------------
__global__ void k_init_nodes() {
    int i = blockIdx.x * blockDim.x + threadIdx.x;
    if (i < Nn) { d_deg[i] = 0.f; d_la[i] = 0.f; }
}

// ---------------- degree + self-loop attr sum -------------------------------
__global__ void k_deg(const int* __restrict__ ei, const float* __restrict__ ea) {
    int e = blockIdx.x * blockDim.x + threadIdx.x;
    if (e >= Ee) return;
    int dst = ei[Ee + e];
    atomicAdd(&d_deg[dst], 1.f);
    atomicAdd(&d_la[dst], ea[e]);
}

// ---------------- CSR build: block scan over counts (cnt = deg + 1) ---------
__global__ void k_scan1() {
    __shared__ int s[256];
    int t = threadIdx.x;
    int i = blockIdx.x * 256 + t;
    int v = (i < Nn) ? ((int)d_deg[i] + 1) : 0;
    s[t] = v;
    __syncthreads();
#pragma unroll
    for (int off = 1; off < 256; off <<= 1) {
        int a = (t >= off) ? s[t - off] : 0;
        __syncthreads();
        s[t] += a;
        __syncthreads();
    }
    if (i < Nn) d_off[i] = s[t] - v;          // block-local exclusive
    if (t == 255) d_btot[blockIdx.x] = s[255];
}

// block offsets recomputed locally + finalize offsets
__global__ void k_scan3() {
    int i = blockIdx.x * blockDim.x + threadIdx.x;
    if (i >= Nn) return;
    int blk = i >> 8;
    int boff = 0;
    for (int b = 0; b < blk; b++) boff += d_btot[b];
    int o = d_off[i] + boff;
    d_off[i] = o;
    d_cur[i] = o;
}

// fill CSR slots with materialized (src, edge_attr); self-loop attr = mean
__global__ void k_fill(const int* __restrict__ ei, const float* __restrict__ ea) {
    int e = blockIdx.x * blockDim.x + threadIdx.x;
    if (e >= EA) return;
    int dst, src; float eav;
    if (e < Ee) { dst = ei[Ee + e]; src = ei[e]; eav = ea[e]; }
    else        { dst = e - Ee;     src = dst;
                  eav = d_la[dst] / fmaxf(d_deg[dst], 1.f); }
    int pos = atomicAdd(&d_cur[dst], 1);
    d_csrc[pos] = src;
    d_cea[pos] = eav;
}

// ---------------- conv1 linear (IN=4 -> 256), xl & xr fused -----------------
__global__ void k_lin1(const float* __restrict__ x,
                       const float* __restrict__ Wl, const float* __restrict__ bl,
                       const float* __restrict__ Wr, const float* __restrict__ br) {
    int idx = blockIdx.x * blockDim.x + threadIdx.x;
    if (idx >= Nn * HIDC) return;
    int n = idx >> 8, c = idx & 255;
    float4 xv = *(const float4*)(x + n * 4);   // LDG.128, broadcast within node
    float l = bl[c] + xv.x * Wl[c] + xv.y * Wl[256 + c] + xv.z * Wl[512 + c] + xv.w * Wl[768 + c];
    float r = br[c] + xv.x * Wr[c] + xv.y * Wr[256 + c] + xv.z * Wr[512 + c] + xv.w * Wr[768 + c];
    d_xl1[idx] = l;
    d_xr1[idx] = r;
}

// ---------------- fused GATv2 layer 1 (4 heads): online softmax, pipelined --
__global__ void k_gat1(const float* __restrict__ We, const float* __restrict__ att,
                       const float* __restrict__ bias, const float* __restrict__ g,
                       const float* __restrict__ be) {
    int gt = blockIdx.x * blockDim.x + threadIdx.x;
    int n = gt >> 5;
    if (n >= Nn) return;
    int lane = gt & 31;
    int base = d_off[n];
    int cnt = (int)d_deg[n] + 1;
    int c0 = lane * 8;

    // per-node operands, loaded once into registers
    const float4* pxr = (const float4*)(d_xr1 + n * HIDC + c0);
    float4 xr0 = pxr[0], xr1v = pxr[1];
    const float4* pw = (const float4*)(We + c0);
    float4 w0 = pw[0], w1 = pw[1];
    const float4* pa = (const float4*)(att + c0);
    float4 t0 = pa[0], t1 = pa[1];

    float m = __int_as_float(0xff800000);
    float s = 0.f;
    float a0 = 0.f, a1 = 0.f, a2 = 0.f, a3 = 0.f, a4 = 0.f, a5 = 0.f, a6 = 0.f, a7 = 0.f;

    // stage 0 preload
    int src = d_csrc[base];
    float eav = d_cea[base];
    const float4* px = (const float4*)(d_xl1 + src * HIDC + c0);
    float4 v0 = px[0], v1 = px[1];

    for (int i = 0; i < cnt; i++) {
        // prefetch next edge (issued before this edge's compute chain)
        float4 nv0 = make_float4(0.f, 0.f, 0.f, 0.f);
        float4 nv1 = make_float4(0.f, 0.f, 0.f, 0.f);
        float neav = 0.f;
        if (i + 1 < cnt) {
            int nsrc = d_csrc[base + i + 1];
            neav = d_cea[base + i + 1];
            const float4* pn = (const float4*)(d_xl1 + nsrc * HIDC + c0);
            nv0 = pn[0]; nv1 = pn[1];
        }
        float part = t0.x * lrelu(v0.x + xr0.x + eav * w0.x)
                   + t0.y * lrelu(v0.y + xr0.y + eav * w0.y)
                   + t0.z * lrelu(v0.z + xr0.z + eav * w0.z)
                   + t0.w * lrelu(v0.w + xr0.w + eav * w0.w)
                   + t1.x * lrelu(v1.x + xr1v.x + eav * w1.x)
                   + t1.y * lrelu(v1.y + xr1v.y + eav * w1.y)
                   + t1.z * lrelu(v1.z + xr1v.z + eav * w1.z)
                   + t1.w * lrelu(v1.w + xr1v.w + eav * w1.w);
        // sum within each 8-lane group (= one head); all lanes get group total
        part += __shfl_xor_sync(0xffffffff, part, 4, 8);
        part += __shfl_xor_sync(0xffffffff, part, 2, 8);
        part += __shfl_xor_sync(0xffffffff, part, 1, 8);
        // online softmax update (per lane; identical within each 8-lane group)
        float nm = fmaxf(m, part);
        float corr = __expf(m - nm);      // first iter: exp(-inf) = 0
        float el = __expf(part - nm);
        m = nm;
        s = s * corr + el;
        a0 = a0 * corr + el * v0.x; a1 = a1 * corr + el * v0.y;
        a2 = a2 * corr + el * v0.z; a3 = a3 * corr + el * v0.w;
        a4 = a4 * corr + el * v1.x; a5 = a5 * corr + el * v1.y;
        a6 = a6 * corr + el * v1.z; a7 = a7 * corr + el * v1.w;
        v0 = nv0; v1 = nv1; eav = neav;
    }
    float rs = 1.f / s;

    // ---- epilogue: normalize, + bias, LayerNorm, ReLU
    float v[8] = {a0 * rs, a1 * rs, a2 * rs, a3 * rs, a4 * rs, a5 * rs, a6 * rs, a7 * rs};
#pragma unroll
    for (int q = 0; q < 8; q++) v[q] += bias[c0 + q];
    float ssum = 0.f;
#pragma unroll
    for (int q = 0; q < 8; q++) ssum += v[q];
#pragma unroll
    for (int o = 16; o > 0; o >>= 1) ssum += __shfl_xor_sync(0xffffffff, ssum, o);
    float mu = ssum * (1.f / 256.f);
    float sq = 0.f;
#pragma unroll
    for (int q = 0; q < 8; q++) { float d = v[q] - mu; sq += d * d; }
#pragma unroll
    for (int o = 16; o > 0; o >>= 1) sq += __shfl_xor_sync(0xffffffff, sq, o);
    float rstd = rsqrtf(sq * (1.f / 256.f) + 1e-5f);
    float* pout = d_h1ln + n * HIDC + c0;
#pragma unroll
    for (int q = 0; q < 8; q++) {
        float y = (v[q] - mu) * rstd * g[c0 + q] + be[c0 + q];
        pout[q] = fmaxf(y, 0.f);
    }
}

// ---------------- conv2 linear (256x256 GEMM, xl & xr fused) ----------------
// packed f32x2 FMA over (even-k, odd-k) partial sums; hs operand = LDS.64 broadcast
__global__ void k_lin2(const float* __restrict__ Wl, const float* __restrict__ bl,
                       const float* __restrict__ Wr, const float* __restrict__ br) {
    __shared__ float hs[16][HIDC];
    int row0 = blockIdx.x * 16;
    int t = threadIdx.x;
    for (int i = t; i < 16 * HIDC; i += 256) {
        int r = i >> 8, c = i & 255;
        int n = row0 + r;
        hs[r][c] = (n < Nn) ? d_h1ln[n * HIDC + c] : 0.f;
    }
    __syncthreads();
    unsigned long long accl[16], accr[16];
#pragma unroll
    for (int r = 0; r < 16; r++) { accl[r] = 0ull; accr[r] = 0ull; }
#pragma unroll 2
    for (int k = 0; k < HIDC; k += 2) {
        unsigned long long wl2 = pack_f32x2(Wl[k * HIDC + t], Wl[(k + 1) * HIDC + t]);
        unsigned long long wr2 = pack_f32x2(Wr[k * HIDC + t], Wr[(k + 1) * HIDC + t]);
#pragma unroll
        for (int r = 0; r < 16; r++) {
            unsigned long long hv2 = *(const unsigned long long*)&hs[r][k];  // LDS.64 broadcast
            fma_f32x2(accl[r], hv2, wl2);
            fma_f32x2(accr[r], hv2, wr2);
        }
    }
    float blv = bl[t], brv = br[t];
#pragma unroll
    for (int r = 0; r < 16; r++) {
        int n = row0 + r;
        if (n < Nn) {
            d_xl2[n * HIDC + t] = hsum_f32x2(accl[r]) + blv;
            d_xr2[n * HIDC + t] = hsum_f32x2(accr[r]) + brv;
        }
    }
}

// ---------------- fused GATv2 layer 2 (1 head): online softmax, pipelined ---
__global__ void k_gat2(const float* __restrict__ We, const float* __restrict__ att,
                       const float* __restrict__ bias, const float* __restrict__ g,
                       const float* __restrict__ be) {
    int gt = blockIdx.x * blockDim.x + threadIdx.x;
    int n = gt >> 5;
    if (n >= Nn) return;
    int lane = gt & 31;
    int base = d_off[n];
    int cnt = (int)d_deg[n] + 1;
    int c0 = lane * 8;

    const float4* pxr = (const float4*)(d_xr2 + n * HIDC + c0);
    float4 xr0 = pxr[0], xr1v = pxr[1];
    const float4* pw = (const float4*)(We + c0);
    float4 w0 = pw[0], w1 = pw[1];
    const float4* pa = (const float4*)(att + c0);
    float4 t0 = pa[0], t1 = pa[1];

    float m = __int_as_float(0xff800000);
    float s = 0.f;
    float a0 = 0.f, a1 = 0.f, a2 = 0.f, a3 = 0.f, a4 = 0.f, a5 = 0.f, a6 = 0.f, a7 = 0.f;

    int src = d_csrc[base];
    float eav = d_cea[base];
    const float4* px = (const float4*)(d_xl2 + src * HIDC + c0);
    float4 v0 = px[0], v1 = px[1];

    for (int i = 0; i < cnt; i++) {
        float4 nv0 = make_float4(0.f, 0.f, 0.f, 0.f);
        float4 nv1 = make_float4(0.f, 0.f, 0.f, 0.f);
        float neav = 0.f;
        if (i + 1 < cnt) {
            int nsrc = d_csrc[base + i + 1];
            neav = d_cea[base + i + 1];
            const float4* pn = (const float4*)(d_xl2 + nsrc * HIDC + c0);
            nv0 = pn[0]; nv1 = pn[1];
        }
        float part = t0.x * lrelu(v0.x + xr0.x + eav * w0.x)
                   + t0.y * lrelu(v0.y + xr0.y + eav * w0.y)
                   + t0.z * lrelu(v0.z + xr0.z + eav * w0.z)
                   + t0.w * lrelu(v0.w + xr0.w + eav * w0.w)
                   + t1.x * lrelu(v1.x + xr1v.x + eav * w1.x)
                   + t1.y * lrelu(v1.y + xr1v.y + eav * w1.y)
                   + t1.z * lrelu(v1.z + xr1v.z + eav * w1.z)
                   + t1.w * lrelu(v1.w + xr1v.w + eav * w1.w);
        // full-warp sum (single head); all lanes get total
#pragma unroll
        for (int o = 16; o > 0; o >>= 1) part += __shfl_xor_sync(0xffffffff, part, o);
        float nm = fmaxf(m, part);
        float corr = __expf(m - nm);
        float el = __expf(part - nm);
        m = nm;
        s = s * corr + el;
        a0 = a0 * corr + el * v0.x; a1 = a1 * corr + el * v0.y;
        a2 = a2 * corr + el * v0.z; a3 = a3 * corr + el * v0.w;
        a4 = a4 * corr + el * v1.x; a5 = a5 * corr + el * v1.y;
        a6 = a6 * corr + el * v1.z; a7 = a7 * corr + el * v1.w;
        v0 = nv0; v1 = nv1; eav = neav;
    }
    float rs = 1.f / s;

    float v[8] = {a0 * rs, a1 * rs, a2 * rs, a3 * rs, a4 * rs, a5 * rs, a6 * rs, a7 * rs};
#pragma unroll
    for (int q = 0; q < 8; q++) v[q] += bias[c0 + q];
    float ssum = 0.f;
#pragma unroll
    for (int q = 0; q < 8; q++) ssum += v[q];
#pragma unroll
    for (int o = 16; o > 0; o >>= 1) ssum += __shfl_xor_sync(0xffffffff, ssum, o);
    float mu = ssum * (1.f / 256.f);
    float sq = 0.f;
#pragma unroll
    for (int q = 0; q < 8; q++) { float d = v[q] - mu; sq += d * d; }
#pragma unroll
    for (int o = 16; o > 0; o >>= 1) sq += __shfl_xor_sync(0xffffffff, sq, o);
    float rstd = rsqrtf(sq * (1.f / 256.f) + 1e-5f);
    float* pout = d_h2ln + n * HIDC + c0;
#pragma unroll
    for (int q = 0; q < 8; q++) {
        float y = (v[q] - mu) * rstd * g[c0 + q] + be[c0 + q];
        pout[q] = fmaxf(y, 0.f);
    }
}

// ---------------- policy head: 16 nodes per block, f32x2 FMA ----------------
__global__ void k_policy(const float* __restrict__ Wp1, const float* __restrict__ bp1,
                         const float* __restrict__ Wp2, const float* __restrict__ bp2) {
    __shared__ float hs[16][HIDC];
    __shared__ float so[16][4];
    int row0 = blockIdx.x * 16;
    int t = threadIdx.x;   // 128 threads, one per mid channel
    for (int i = t; i < 16 * HIDC; i += 128) {
        int r = i >> 8, c = i & 255;
        int n = row0 + r;
        hs[r][c] = (n < Nn) ? d_h2ln[n * HIDC + c] : 0.f;
    }
    if (t < 64) so[t >> 2][t & 3] = 0.f;
    __syncthreads();
    unsigned long long acc2[16];
#pragma unroll
    for (int r = 0; r < 16; r++) acc2[r] = 0ull;
#pragma unroll 2
    for (int k = 0; k < HIDC; k += 2) {
        unsigned long long w2 = pack_f32x2(Wp1[k * 128 + t], Wp1[(k + 1) * 128 + t]);
#pragma unroll
        for (int r = 0; r < 16; r++) {
            unsigned long long hv2 = *(const unsigned long long*)&hs[r][k];
            fma_f32x2(acc2[r], hv2, w2);
        }
    }
    float b1v = bp1[t];
    float w0 = Wp2[t * 4 + 0], w1 = Wp2[t * 4 + 1], w2s = Wp2[t * 4 + 2], w3 = Wp2[t * 4 + 3];
#pragma unroll
    for (int r = 0; r < 16; r++) {
        float a = fmaxf(hsum_f32x2(acc2[r]) + b1v, 0.f);
        atomicAdd(&so[r][0], a * w0);
        atomicAdd(&so[r][1], a * w1);
        atomicAdd(&so[r][2], a * w2s);
        atomicAdd(&so[r][3], a * w3);
    }
    __syncthreads();
    if (t < 64) {
        int r = t >> 2, o = t & 3;
        int n = row0 + r;
        if (n < Nn) d_pol[n * 4 + o] = so[r][o] + bp2[o];
    }
}

// ---------------- global softmax over 40000 logits (single block) -----------
__global__ void k_softmax(float* __restrict__ out) {
    __shared__ float sm[32];
    int t = threadIdx.x;          // 1024 threads = 32 warps
    int lane = t & 31, w = t >> 5;

    // pass 1: max
    float v = __int_as_float(0xff800000);
    for (int j = t; j < Nn * INC; j += 1024) v = fmaxf(v, d_pol[j]);
#pragma unroll
    for (int o = 16; o > 0; o >>= 1) v = fmaxf(v, __shfl_xor_sync(0xffffffff, v, o));
    if (lane == 0) sm[w] = v;
    __syncthreads();
    v = sm[lane];                 // all 32 entries valid
#pragma unroll
    for (int o = 16; o > 0; o >>= 1) v = fmaxf(v, __shfl_xor_sync(0xffffffff, v, o));
    __syncthreads();
    if (t == 0) sm[0] = v;
    __syncthreads();
    float gmax = sm[0];

    // pass 2: exp + sum
    float part = 0.f;
    for (int j = t; j < Nn * INC; j += 1024) {
        float ex = __expf(d_pol[j] - gmax);
        out[j] = ex;
        part += ex;
    }
    __syncthreads();
#pragma unroll
    for (int o = 16; o > 0; o >>= 1) part += __shfl_xor_sync(0xffffffff, part, o);
    if (lane == 0) sm[w] = part;
    __syncthreads();
    part = sm[lane];
#pragma unroll
    for (int o = 16; o > 0; o >>= 1) part += __shfl_xor_sync(0xffffffff, part, o);
    __syncthreads();
    if (t == 0) sm[0] = 1.f / part;
    __syncthreads();
    float rs = sm[0];

    // pass 3: divide
    for (int j = t; j < Nn * INC; j += 1024) out[j] *= rs;
}

// ---------------------------------------------------------------------------
extern "C" void kernel_launch(void* const* d_in, const int* in_sizes, int n_in,
                              void* d_out, int out_size) {
    const float* x    = (const float*)d_in[0];
    const int*   ei   = (const int*)  d_in[1];
    const float* ea   = (const float*)d_in[2];
    const float* Wl1  = (const float*)d_in[3];
    const float* bl1  = (const float*)d_in[4];
    const float* Wr1  = (const float*)d_in[5];
    const float* br1  = (const float*)d_in[6];
    const float* We1  = (const float*)d_in[7];
    const float* att1 = (const float*)d_in[8];
    const float* bias1= (const float*)d_in[9];
    const float* g1   = (const float*)d_in[10];
    const float* be1  = (const float*)d_in[11];
    const float* Wl2  = (const float*)d_in[12];
    const float* bl2  = (const float*)d_in[13];
    const float* Wr2  = (const float*)d_in[14];
    const float* br2  = (const float*)d_in[15];
    const float* We2  = (const float*)d_in[16];
    const float* att2 = (const float*)d_in[17];
    const float* bias2= (const float*)d_in[18];
    const float* g2   = (const float*)d_in[19];
    const float* be2  = (const float*)d_in[20];
    const float* Wp1  = (const float*)d_in[21];
    const float* bp1  = (const float*)d_in[22];
    const float* Wp2  = (const float*)d_in[23];
    const float* bp2  = (const float*)d_in[24];
    float* out = (float*)d_out;

    const int T = 256;
    const int SCAN_BLOCKS = (Nn + 255) / 256;   // 40
    k_init_nodes<<<(Nn + T - 1) / T, T>>>();
    k_deg<<<(Ee + T - 1) / T, T>>>(ei, ea);
    // CSR build (materialized src + edge attr per slot)
    k_scan1<<<SCAN_BLOCKS, 256>>>();
    k_scan3<<<SCAN_BLOCKS, 256>>>();
    k_fill<<<(EA + T - 1) / T, T>>>(ei, ea);
    // layer 1
    k_lin1<<<(Nn * HIDC + T - 1) / T, T>>>(x, Wl1, bl1, Wr1, br1);
    k_gat1<<<(Nn * 32 + T - 1) / T, T>>>(We1, att1, bias1, g1, be1);
    // layer 2
    k_lin2<<<(Nn + 15) / 16, T>>>(Wl2, bl2, Wr2, br2);
    k_gat2<<<(Nn * 32 + T - 1) / T, T>>>(We2, att2, bias2, g2, be2);
    // heads
    k_policy<<<(Nn + 15) / 16, 128>>>(Wp1, bp1, Wp2, bp2);
    k_softmax<<<1, 1024>>>(out);
}